// round 8
// baseline (speedup 1.0000x reference)
#include <cuda_runtime.h>
#include <cuda_bf16.h>
#include <mma.h>

using namespace nvcuda;

// Problem shape (fixed by the dataset instance)
constexpr int B  = 256;
constexpr int S  = 128;
constexpr int H  = 768;
constexpr int D  = S * H;      // 98304

// GEMM tiling
constexpr int KC     = 64;                 // K elems staged per iteration
constexpr int LDT    = 72;                 // padded smem leading dim (bf16 elems)
constexpr int KSPLIT = 64;                 // grid.z
constexpr int KITERS = D / KC / KSPLIT;    // 24

// Device scratch (allocation-free rule: __device__ globals)
__device__ float g_part[(size_t)KSPLIT * B * B];   // split-K partial dot products (16.8 MB)
__device__ float g_s2[B];
__device__ float g_t2[B];
__device__ float g_acc;

__inline__ __device__ float block_reduce_sum(float v) {
    __shared__ float sm[32];
    for (int o = 16; o > 0; o >>= 1) v += __shfl_down_sync(0xffffffffu, v, o);
    int lane = threadIdx.x & 31, w = threadIdx.x >> 5;
    if (lane == 0) sm[w] = v;
    __syncthreads();
    int nw = (blockDim.x + 31) >> 5;
    if (w == 0) {
        v = (lane < nw) ? sm[lane] : 0.f;
        for (int o = 16; o > 0; o >>= 1) v += __shfl_down_sync(0xffffffffu, v, o);
    }
    __syncthreads();
    return v;  // valid on thread 0
}

__global__ void zero_kernel() {
    int t = threadIdx.x;
    g_s2[t] = 0.f;
    g_t2[t] = 0.f;
    if (t == 0) g_acc = 0.f;
}

// Fused fp32->bf16 + split-K bf16 wmma GEMM + row-norm accumulation.
// part[z][i][j] = sum_{k in slice z} sf[i][k]*tf[j][k]   (bf16 inputs, fp32 accum)
// g_s2[i] += sum_{k in slice z} sf[i][k]^2 (fp32, only by==0 CTAs; exactly-once over z)
// g_t2[j] analogous (only bx==0 CTAs).
__global__ void __launch_bounds__(256) gemm_kernel(const float* __restrict__ s_feat,
                                                   const float* __restrict__ t_feat) {
    __shared__ __nv_bfloat16 smA[128 * LDT];
    __shared__ __nv_bfloat16 smB[128 * LDT];

    const int m0 = blockIdx.x * 128;
    const int n0 = blockIdx.y * 128;
    const int kbase = blockIdx.z * KITERS * KC;
    const int tid = threadIdx.x, warp = tid >> 5, lane = tid & 31;
    const int wm = warp & 3;   // 4 warps across M (32 rows each)
    const int wn = warp >> 2;  // 2 warps across N (64 cols each)

    float nA[4] = {0.f, 0.f, 0.f, 0.f};
    float nB[4] = {0.f, 0.f, 0.f, 0.f};

    wmma::fragment<wmma::accumulator, 16, 16, 16, float> acc[2][4];
#pragma unroll
    for (int i = 0; i < 2; i++)
#pragma unroll
        for (int j = 0; j < 4; j++) wmma::fill_fragment(acc[i][j], 0.f);

    for (int it = 0; it < KITERS; ++it) {
        const int k0 = kbase + it * KC;
        // stage 128x64: load fp32, accumulate norms, convert to bf16, store to smem
#pragma unroll
        for (int u = 0; u < 4; u++) {
            const int c = tid + 256 * u;
            const int row = c >> 3, seg = c & 7;

            const float4* pa = (const float4*)(s_feat + (size_t)(m0 + row) * D + k0 + seg * 8);
            float4 a0 = pa[0], a1 = pa[1];
            nA[u] += a0.x * a0.x + a0.y * a0.y + a0.z * a0.z + a0.w * a0.w
                   + a1.x * a1.x + a1.y * a1.y + a1.z * a1.z + a1.w * a1.w;
            __nv_bfloat162 h0 = __float22bfloat162_rn(make_float2(a0.x, a0.y));
            __nv_bfloat162 h1 = __float22bfloat162_rn(make_float2(a0.z, a0.w));
            __nv_bfloat162 h2 = __float22bfloat162_rn(make_float2(a1.x, a1.y));
            __nv_bfloat162 h3 = __float22bfloat162_rn(make_float2(a1.z, a1.w));
            uint4 wA;
            wA.x = *reinterpret_cast<unsigned*>(&h0);
            wA.y = *reinterpret_cast<unsigned*>(&h1);
            wA.z = *reinterpret_cast<unsigned*>(&h2);
            wA.w = *reinterpret_cast<unsigned*>(&h3);
            *(uint4*)&smA[row * LDT + seg * 8] = wA;

            const float4* pb = (const float4*)(t_feat + (size_t)(n0 + row) * D + k0 + seg * 8);
            float4 b0 = pb[0], b1 = pb[1];
            nB[u] += b0.x * b0.x + b0.y * b0.y + b0.z * b0.z + b0.w * b0.w
                   + b1.x * b1.x + b1.y * b1.y + b1.z * b1.z + b1.w * b1.w;
            __nv_bfloat162 g0 = __float22bfloat162_rn(make_float2(b0.x, b0.y));
            __nv_bfloat162 g1 = __float22bfloat162_rn(make_float2(b0.z, b0.w));
            __nv_bfloat162 g2 = __float22bfloat162_rn(make_float2(b1.x, b1.y));
            __nv_bfloat162 g3 = __float22bfloat162_rn(make_float2(b1.z, b1.w));
            uint4 wB;
            wB.x = *reinterpret_cast<unsigned*>(&g0);
            wB.y = *reinterpret_cast<unsigned*>(&g1);
            wB.z = *reinterpret_cast<unsigned*>(&g2);
            wB.w = *reinterpret_cast<unsigned*>(&g3);
            *(uint4*)&smB[row * LDT + seg * 8] = wB;
        }
        __syncthreads();
#pragma unroll
        for (int kk = 0; kk < KC; kk += 16) {
            wmma::fragment<wmma::matrix_a, 16, 16, 16, __nv_bfloat16, wmma::row_major> af[2];
            wmma::fragment<wmma::matrix_b, 16, 16, 16, __nv_bfloat16, wmma::col_major> bf[4];
#pragma unroll
            for (int i = 0; i < 2; i++)
                wmma::load_matrix_sync(af[i], &smA[(wm * 32 + i * 16) * LDT + kk], LDT);
#pragma unroll
            for (int j = 0; j < 4; j++)
                wmma::load_matrix_sync(bf[j], &smB[(wn * 64 + j * 16) * LDT + kk], LDT);
#pragma unroll
            for (int i = 0; i < 2; i++)
#pragma unroll
                for (int j = 0; j < 4; j++)
                    wmma::mma_sync(acc[i][j], af[i], bf[j], acc[i][j]);
        }
        __syncthreads();
    }

    // Row-norm reduction: 8 consecutive lanes (segs) share one row.
#pragma unroll
    for (int u = 0; u < 4; u++) {
        const int row = (tid >> 3) + 32 * u;
        float va = nA[u];
        va += __shfl_down_sync(0xffffffffu, va, 4, 8);
        va += __shfl_down_sync(0xffffffffu, va, 2, 8);
        va += __shfl_down_sync(0xffffffffu, va, 1, 8);
        if ((lane & 7) == 0 && blockIdx.y == 0) atomicAdd(&g_s2[m0 + row], va);
        float vb = nB[u];
        vb += __shfl_down_sync(0xffffffffu, vb, 4, 8);
        vb += __shfl_down_sync(0xffffffffu, vb, 2, 8);
        vb += __shfl_down_sync(0xffffffffu, vb, 1, 8);
        if ((lane & 7) == 0 && blockIdx.x == 0) atomicAdd(&g_t2[n0 + row], vb);
    }

    // Epilogue: plain stores of this z-slice's partials (no atomics)
    float* base = g_part + (size_t)blockIdx.z * B * B;
#pragma unroll
    for (int i = 0; i < 2; i++)
#pragma unroll
        for (int j = 0; j < 4; j++) {
            const int r0 = m0 + wm * 32 + i * 16;
            const int c0 = n0 + wn * 64 + j * 16;
            wmma::store_matrix_sync(base + (size_t)r0 * B + c0, acc[i][j], B,
                                    wmma::mem_row_major);
        }
}

// Warp-per-row: reduce split-K partials, build masked sq, take k smallest, sum.
__global__ void topk_kernel(const int* __restrict__ labels, const int* __restrict__ kptr) {
    const int warp = threadIdx.x >> 5, lane = threadIdx.x & 31;
    const int i = blockIdx.x * 8 + warp;
    const int li = labels[i];
    const float BIG = 3e38f;

    float v[8];
#pragma unroll
    for (int t = 0; t < 8; t++) v[t] = 0.f;
    for (int z = 0; z < KSPLIT; z++) {
        const float* pz = g_part + ((size_t)z * B + i) * B;
#pragma unroll
        for (int t = 0; t < 8; t++) v[t] += pz[lane + 32 * t];
    }
    const float s2i = g_s2[i];
#pragma unroll
    for (int t = 0; t < 8; t++) {
        const int j = lane + 32 * t;
        v[t] = (labels[j] == li) ? fmaxf(s2i + g_t2[j] - 2.f * v[t], 0.f) : BIG;
    }

    int k = kptr ? kptr[0] : 5;
    if (k > B) k = B;
    if (k < 0) k = 0;

    float ssum = 0.f;
    for (int r = 0; r < k; ++r) {
        float m = v[0];
#pragma unroll
        for (int t = 1; t < 8; t++) m = fminf(m, v[t]);
#pragma unroll
        for (int off = 16; off > 0; off >>= 1)
            m = fminf(m, __shfl_xor_sync(0xffffffffu, m, off));
        if (m >= 1e37f) break;  // no more valid neighbors (group < k)
        bool has = false;
#pragma unroll
        for (int t = 0; t < 8; t++) has |= (v[t] == m);
        unsigned bal = __ballot_sync(0xffffffffu, has);
        int win = __ffs(bal) - 1;
        if (lane == win) {
            bool done = false;
#pragma unroll
            for (int t = 0; t < 8; t++)
                if (!done && v[t] == m) { v[t] = BIG; done = true; }
        }
        if (lane == 0) ssum += m;
    }
    if (lane == 0) atomicAdd(&g_acc, ssum);
}

// Tiny losses + final assembly (NL == 2 hardcoded)
__global__ void final_kernel(const float* __restrict__ t_logits,
                             const float* __restrict__ s_logits,
                             const int* __restrict__ labels,
                             const int* __restrict__ tptr,
                             float* __restrict__ out) {
    const int b = threadIdx.x;  // 256 threads
    const float T = tptr ? (float)tptr[0] : 4.f;

    float s0 = s_logits[2 * b], s1 = s_logits[2 * b + 1];
    float m = fmaxf(s0, s1);
    float lse = m + logf(expf(s0 - m) + expf(s1 - m));
    int lab = labels[b];
    float tr = lse - (lab ? s1 : s0);

    float t0 = t_logits[2 * b] / T, t1 = t_logits[2 * b + 1] / T;
    float mt = fmaxf(t0, t1);
    float e0 = expf(t0 - mt), e1 = expf(t1 - mt);
    float Z = e0 + e1;
    float p0 = e0 / Z, p1 = e1 / Z;
    float q0 = s0 / T, q1 = s1 / T;
    float mq = fmaxf(q0, q1);
    float lseq = mq + logf(expf(q0 - mq) + expf(q1 - mq));
    float soft = p0 * (logf(p0) - (q0 - lseq)) + p1 * (logf(p1) - (q1 - lseq));

    float trs = block_reduce_sum(tr);
    float sfs = block_reduce_sum(soft);
    if (b == 0) {
        out[0] = trs / (float)B;
        out[1] = sfs / (float)B * T * T;
        out[2] = g_acc / (float)D;
    }
}

extern "C" void kernel_launch(void* const* d_in, const int* in_sizes, int n_in,
                              void* d_out, int out_size) {
    const float* t_logits = (const float*)d_in[0];
    const float* s_logits = (const float*)d_in[1];
    const float* t_feat   = (const float*)d_in[2];
    const float* s_feat   = (const float*)d_in[3];
    const int*   labels   = (const int*)d_in[4];            // int32 (JAX x64 disabled)
    const int*   kptr     = (n_in > 5) ? (const int*)d_in[5] : nullptr;
    const int*   tptr     = (n_in > 6) ? (const int*)d_in[6] : nullptr;
    float* out = (float*)d_out;

    zero_kernel<<<1, 256>>>();
    gemm_kernel<<<dim3(2, 2, KSPLIT), 256>>>(s_feat, t_feat);
    topk_kernel<<<32, 256>>>(labels, kptr);
    final_kernel<<<1, 256>>>(t_logits, s_logits, labels, tptr, out);
}

// round 10
// speedup vs baseline: 1.1664x; 1.1664x over previous
#include <cuda_runtime.h>
#include <cuda_bf16.h>
#include <mma.h>

using namespace nvcuda;

// Problem shape (fixed by the dataset instance)
constexpr int B  = 256;
constexpr int S  = 128;
constexpr int H  = 768;
constexpr int D  = S * H;      // 98304

// GEMM tiling
constexpr int KC     = 64;                 // K elems staged per iteration
constexpr int LDT    = 72;                 // padded smem leading dim (bf16 elems)
constexpr int KSPLIT = 37;                 // 4*37 = 148 CTAs = one full wave
constexpr int NCHUNK = D / KC;             // 1536 = 19*42 + 18*41

// Device scratch (allocation-free rule: __device__ globals)
__device__ float g_part[(size_t)KSPLIT * B * B];   // split-K partials (9.7 MB)
__device__ float g_s2p[KSPLIT * B];                // per-z row-norm partials (student)
__device__ float g_t2p[KSPLIT * B];                // per-z row-norm partials (teacher)
__device__ float g_acc = 0.f;                      // self-resetting accumulator
__device__ int   g_counter = 0;                    // self-resetting block counter

__inline__ __device__ float block_reduce_sum(float v) {
    __shared__ float sm[32];
    for (int o = 16; o > 0; o >>= 1) v += __shfl_down_sync(0xffffffffu, v, o);
    int lane = threadIdx.x & 31, w = threadIdx.x >> 5;
    if (lane == 0) sm[w] = v;
    __syncthreads();
    int nw = (blockDim.x + 31) >> 5;
    if (w == 0) {
        v = (lane < nw) ? sm[lane] : 0.f;
        for (int o = 16; o > 0; o >>= 1) v += __shfl_down_sync(0xffffffffu, v, o);
    }
    __syncthreads();
    return v;  // valid on thread 0
}

// Fused fp32->bf16 + split-K bf16 wmma GEMM + row-norm partials.
// Software-pipelined: next tile's LDGs are issued before the MMA section so
// DRAM latency is covered by tensor work.
__global__ void __launch_bounds__(256) gemm_kernel(const float* __restrict__ s_feat,
                                                   const float* __restrict__ t_feat) {
    __shared__ __nv_bfloat16 smA[128 * LDT];
    __shared__ __nv_bfloat16 smB[128 * LDT];

    const int m0 = blockIdx.x * 128;
    const int n0 = blockIdx.y * 128;
    const int z  = blockIdx.z;
    int it0, niter;
    if (z < 19) { niter = 42; it0 = z * 42; }
    else        { niter = 41; it0 = 798 + (z - 19) * 41; }

    const int tid = threadIdx.x, warp = tid >> 5, lane = tid & 31;
    const int wm = warp & 3;   // 4 warps across M (32 rows each)
    const int wn = warp >> 2;  // 2 warps across N (64 cols each)

    const int row0 = tid >> 3;       // 0..31 (row = row0 + 32*u)
    const int seg  = tid & 7;        // 8 segs x 8 floats = KC
    const size_t aoff = (size_t)(m0 + row0) * D + seg * 8;
    const size_t boff = (size_t)(n0 + row0) * D + seg * 8;

    float4 bA[8], bB[8];             // register prefetch buffers (64 floats)
    float nA[4] = {0.f, 0.f, 0.f, 0.f};
    float nB[4] = {0.f, 0.f, 0.f, 0.f};

    wmma::fragment<wmma::accumulator, 16, 16, 16, float> acc[2][4];
#pragma unroll
    for (int i = 0; i < 2; i++)
#pragma unroll
        for (int j = 0; j < 4; j++) wmma::fill_fragment(acc[i][j], 0.f);

#define PREFETCH(K0) do {                                                       \
        _Pragma("unroll")                                                       \
        for (int u = 0; u < 4; u++) {                                           \
            const float4* pa = (const float4*)(s_feat + aoff + (size_t)(32 * u) * D + (K0)); \
            bA[2 * u] = pa[0]; bA[2 * u + 1] = pa[1];                           \
            const float4* pb = (const float4*)(t_feat + boff + (size_t)(32 * u) * D + (K0)); \
            bB[2 * u] = pb[0]; bB[2 * u + 1] = pb[1];                           \
        }                                                                       \
    } while (0)

    PREFETCH((size_t)it0 * KC);

    for (int it = 0; it < niter; ++it) {
        // stage registers -> smem (convert to bf16, accumulate norms)
#pragma unroll
        for (int u = 0; u < 4; u++) {
            const int row = row0 + 32 * u;
            float4 a0 = bA[2 * u], a1 = bA[2 * u + 1];
            nA[u] += a0.x * a0.x + a0.y * a0.y + a0.z * a0.z + a0.w * a0.w
                   + a1.x * a1.x + a1.y * a1.y + a1.z * a1.z + a1.w * a1.w;
            __nv_bfloat162 h0 = __float22bfloat162_rn(make_float2(a0.x, a0.y));
            __nv_bfloat162 h1 = __float22bfloat162_rn(make_float2(a0.z, a0.w));
            __nv_bfloat162 h2 = __float22bfloat162_rn(make_float2(a1.x, a1.y));
            __nv_bfloat162 h3 = __float22bfloat162_rn(make_float2(a1.z, a1.w));
            uint4 wA;
            wA.x = *reinterpret_cast<unsigned*>(&h0);
            wA.y = *reinterpret_cast<unsigned*>(&h1);
            wA.z = *reinterpret_cast<unsigned*>(&h2);
            wA.w = *reinterpret_cast<unsigned*>(&h3);
            *(uint4*)&smA[row * LDT + seg * 8] = wA;

            float4 b0 = bB[2 * u], b1 = bB[2 * u + 1];
            nB[u] += b0.x * b0.x + b0.y * b0.y + b0.z * b0.z + b0.w * b0.w
                   + b1.x * b1.x + b1.y * b1.y + b1.z * b1.z + b1.w * b1.w;
            __nv_bfloat162 g0 = __float22bfloat162_rn(make_float2(b0.x, b0.y));
            __nv_bfloat162 g1 = __float22bfloat162_rn(make_float2(b0.z, b0.w));
            __nv_bfloat162 g2 = __float22bfloat162_rn(make_float2(b1.x, b1.y));
            __nv_bfloat162 g3 = __float22bfloat162_rn(make_float2(b1.z, b1.w));
            uint4 wB;
            wB.x = *reinterpret_cast<unsigned*>(&g0);
            wB.y = *reinterpret_cast<unsigned*>(&g1);
            wB.z = *reinterpret_cast<unsigned*>(&g2);
            wB.w = *reinterpret_cast<unsigned*>(&g3);
            *(uint4*)&smB[row * LDT + seg * 8] = wB;
        }
        __syncthreads();

        // issue next tile's loads BEFORE the MMA section (latency hidden by MMA)
        if (it + 1 < niter) PREFETCH((size_t)(it0 + it + 1) * KC);

#pragma unroll
        for (int kk = 0; kk < KC; kk += 16) {
            wmma::fragment<wmma::matrix_a, 16, 16, 16, __nv_bfloat16, wmma::row_major> af[2];
            wmma::fragment<wmma::matrix_b, 16, 16, 16, __nv_bfloat16, wmma::col_major> bf[4];
#pragma unroll
            for (int i = 0; i < 2; i++)
                wmma::load_matrix_sync(af[i], &smA[(wm * 32 + i * 16) * LDT + kk], LDT);
#pragma unroll
            for (int j = 0; j < 4; j++)
                wmma::load_matrix_sync(bf[j], &smB[(wn * 64 + j * 16) * LDT + kk], LDT);
#pragma unroll
            for (int i = 0; i < 2; i++)
#pragma unroll
                for (int j = 0; j < 4; j++)
                    wmma::mma_sync(acc[i][j], af[i], bf[j], acc[i][j]);
        }
        __syncthreads();
    }
#undef PREFETCH

    // Row-norm partials: 8 consecutive lanes share one row; plain stores (no atomics).
#pragma unroll
    for (int u = 0; u < 4; u++) {
        const int row = row0 + 32 * u;
        float va = nA[u];
        va += __shfl_down_sync(0xffffffffu, va, 4, 8);
        va += __shfl_down_sync(0xffffffffu, va, 2, 8);
        va += __shfl_down_sync(0xffffffffu, va, 1, 8);
        if ((lane & 7) == 0 && blockIdx.y == 0) g_s2p[z * B + m0 + row] = va;
        float vb = nB[u];
        vb += __shfl_down_sync(0xffffffffu, vb, 4, 8);
        vb += __shfl_down_sync(0xffffffffu, vb, 2, 8);
        vb += __shfl_down_sync(0xffffffffu, vb, 1, 8);
        if ((lane & 7) == 0 && blockIdx.x == 0) g_t2p[z * B + n0 + row] = vb;
    }

    // Epilogue: plain stores of this z-slice's partials
    float* base = g_part + (size_t)z * B * B;
#pragma unroll
    for (int i = 0; i < 2; i++)
#pragma unroll
        for (int j = 0; j < 4; j++) {
            const int r0 = m0 + wm * 32 + i * 16;
            const int c0 = n0 + wn * 64 + j * 16;
            wmma::store_matrix_sync(base + (size_t)r0 * B + c0, acc[i][j], B,
                                    wmma::mem_row_major);
        }
}

// Warp-per-row: reduce split-K partials + norms, masked top-k, sum.
// The LAST block to finish also computes the logit losses and writes all outputs.
__global__ void __launch_bounds__(256) topk_kernel(const int* __restrict__ labels,
                                                   const int* __restrict__ kptr,
                                                   const float* __restrict__ t_logits,
                                                   const float* __restrict__ s_logits,
                                                   const int* __restrict__ tptr,
                                                   float* __restrict__ out) {
    const int warp = threadIdx.x >> 5, lane = threadIdx.x & 31;
    const int i = blockIdx.x * 8 + warp;
    const int li = labels[i];
    const float BIG = 3e38f;

    // reduce split-K dot partials
    float v[8];
#pragma unroll
    for (int t = 0; t < 8; t++) v[t] = 0.f;
    for (int z = 0; z < KSPLIT; z++) {
        const float* pz = g_part + ((size_t)z * B + i) * B;
#pragma unroll
        for (int t = 0; t < 8; t++) v[t] += pz[lane + 32 * t];
    }
    // reduce norm partials
    float s2i = 0.f;
    for (int z = lane; z < KSPLIT; z += 32) s2i += g_s2p[z * B + i];
#pragma unroll
    for (int off = 16; off > 0; off >>= 1)
        s2i += __shfl_xor_sync(0xffffffffu, s2i, off);
    float t2v[8];
#pragma unroll
    for (int t = 0; t < 8; t++) t2v[t] = 0.f;
    for (int z = 0; z < KSPLIT; z++) {
        const float* tz = g_t2p + z * B;
#pragma unroll
        for (int t = 0; t < 8; t++) t2v[t] += tz[lane + 32 * t];
    }

#pragma unroll
    for (int t = 0; t < 8; t++) {
        const int j = lane + 32 * t;
        v[t] = (labels[j] == li) ? fmaxf(s2i + t2v[t] - 2.f * v[t], 0.f) : BIG;
    }

    int k = kptr ? kptr[0] : 5;
    if (k > B) k = B;
    if (k < 0) k = 0;

    float ssum = 0.f;
    for (int r = 0; r < k; ++r) {
        float m = v[0];
#pragma unroll
        for (int t = 1; t < 8; t++) m = fminf(m, v[t]);
#pragma unroll
        for (int off = 16; off > 0; off >>= 1)
            m = fminf(m, __shfl_xor_sync(0xffffffffu, m, off));
        if (m >= 1e37f) break;  // no more valid neighbors (group < k)
        bool has = false;
#pragma unroll
        for (int t = 0; t < 8; t++) has |= (v[t] == m);
        unsigned bal = __ballot_sync(0xffffffffu, has);
        int win = __ffs(bal) - 1;
        if (lane == win) {
            bool done = false;
#pragma unroll
            for (int t = 0; t < 8; t++)
                if (!done && v[t] == m) { v[t] = BIG; done = true; }
        }
        if (lane == 0) ssum += m;
    }

    // block sum -> global accumulator; last block finishes the job
    __shared__ float wsum[8];
    __shared__ float sh_total;
    __shared__ int   sh_last;
    if (lane == 0) wsum[warp] = ssum;
    __syncthreads();
    if (threadIdx.x == 0) {
        float bs = 0.f;
#pragma unroll
        for (int w = 0; w < 8; w++) bs += wsum[w];
        atomicAdd(&g_acc, bs);
        __threadfence();
        int c = atomicAdd(&g_counter, 1);
        if (c == (int)gridDim.x - 1) {
            sh_total  = atomicAdd(&g_acc, 0.f);  // all adds visible (fenced before counter)
            sh_last   = 1;
            g_counter = 0;   // self-reset for next replay
            g_acc     = 0.f;
        } else {
            sh_last = 0;
        }
    }
    __syncthreads();

    if (sh_last) {
        // fused final: logit losses (NL == 2) with all 256 threads
        const int b = threadIdx.x;
        const float T = tptr ? (float)tptr[0] : 4.f;

        float s0 = s_logits[2 * b], s1 = s_logits[2 * b + 1];
        float m = fmaxf(s0, s1);
        float lse = m + logf(expf(s0 - m) + expf(s1 - m));
        int lab = labels[b];
        float tr = lse - (lab ? s1 : s0);

        float t0 = t_logits[2 * b] / T, t1 = t_logits[2 * b + 1] / T;
        float mt = fmaxf(t0, t1);
        float e0 = expf(t0 - mt), e1 = expf(t1 - mt);
        float Z = e0 + e1;
        float p0 = e0 / Z, p1 = e1 / Z;
        float q0 = s0 / T, q1 = s1 / T;
        float mq = fmaxf(q0, q1);
        float lseq = mq + logf(expf(q0 - mq) + expf(q1 - mq));
        float soft = p0 * (logf(p0) - (q0 - lseq)) + p1 * (logf(p1) - (q1 - lseq));

        float trs = block_reduce_sum(tr);
        float sfs = block_reduce_sum(soft);
        if (b == 0) {
            out[0] = trs / (float)B;
            out[1] = sfs / (float)B * T * T;
            out[2] = sh_total / (float)D;
        }
    }
}

extern "C" void kernel_launch(void* const* d_in, const int* in_sizes, int n_in,
                              void* d_out, int out_size) {
    const float* t_logits = (const float*)d_in[0];
    const float* s_logits = (const float*)d_in[1];
    const float* t_feat   = (const float*)d_in[2];
    const float* s_feat   = (const float*)d_in[3];
    const int*   labels   = (const int*)d_in[4];            // int32 (JAX x64 disabled)
    const int*   kptr     = (n_in > 5) ? (const int*)d_in[5] : nullptr;
    const int*   tptr     = (n_in > 6) ? (const int*)d_in[6] : nullptr;
    float* out = (float*)d_out;

    gemm_kernel<<<dim3(2, 2, KSPLIT), 256>>>(s_feat, t_feat);
    topk_kernel<<<32, 256>>>(labels, kptr, t_logits, s_logits, tptr, out);
}

// round 12
// speedup vs baseline: 1.3906x; 1.1922x over previous
#include <cuda_runtime.h>
#include <cuda_bf16.h>
#include <mma.h>

using namespace nvcuda;

// Problem shape (fixed by the dataset instance)
constexpr int B  = 256;
constexpr int S  = 128;
constexpr int H  = 768;
constexpr int D  = S * H;      // 98304

// GEMM tiling
constexpr int KC     = 64;                 // K elems staged per iteration
constexpr int LDT    = 72;                 // padded smem leading dim (bf16 elems)
constexpr int KSPLIT = 37;                 // 4*37 = 148 CTAs = one full wave

// Device scratch (allocation-free rule: __device__ globals)
__device__ float g_part[(size_t)KSPLIT * B * B];   // split-K partials (9.7 MB)
__device__ float g_s2p[KSPLIT * B];                // per-z row-norm partials (student)
__device__ float g_t2p[KSPLIT * B];                // per-z row-norm partials (teacher)
__device__ float g_acc = 0.f;                      // self-resetting accumulator
__device__ int   g_counter = 0;                    // self-resetting block counter

__inline__ __device__ float block_reduce_sum(float v) {
    __shared__ float sm[32];
    for (int o = 16; o > 0; o >>= 1) v += __shfl_down_sync(0xffffffffu, v, o);
    int lane = threadIdx.x & 31, w = threadIdx.x >> 5;
    if (lane == 0) sm[w] = v;
    __syncthreads();
    int nw = (blockDim.x + 31) >> 5;
    if (w == 0) {
        v = (lane < nw) ? sm[lane] : 0.f;
        for (int o = 16; o > 0; o >>= 1) v += __shfl_down_sync(0xffffffffu, v, o);
    }
    __syncthreads();
    return v;  // valid on thread 0
}

// Fused fp32->bf16 + split-K bf16 wmma GEMM + row-norm partials.
// Software-pipelined: next tile's LDGs are issued before the MMA section so
// DRAM latency is covered by tensor work.
__global__ void __launch_bounds__(256) gemm_kernel(const float* __restrict__ s_feat,
                                                   const float* __restrict__ t_feat) {
    __shared__ __nv_bfloat16 smA[128 * LDT];
    __shared__ __nv_bfloat16 smB[128 * LDT];

    const int m0 = blockIdx.x * 128;
    const int n0 = blockIdx.y * 128;
    const int z  = blockIdx.z;
    int it0, niter;
    if (z < 19) { niter = 42; it0 = z * 42; }
    else        { niter = 41; it0 = 798 + (z - 19) * 41; }

    const int tid = threadIdx.x, warp = tid >> 5, lane = tid & 31;
    const int wm = warp & 3;   // 4 warps across M (32 rows each)
    const int wn = warp >> 2;  // 2 warps across N (64 cols each)

    const int row0 = tid >> 3;       // 0..31 (row = row0 + 32*u)
    const int seg  = tid & 7;        // 8 segs x 8 floats = KC
    const size_t aoff = (size_t)(m0 + row0) * D + seg * 8;
    const size_t boff = (size_t)(n0 + row0) * D + seg * 8;

    float4 bA[8], bB[8];             // register prefetch buffers (64 floats)
    float nA[4] = {0.f, 0.f, 0.f, 0.f};
    float nB[4] = {0.f, 0.f, 0.f, 0.f};

    wmma::fragment<wmma::accumulator, 16, 16, 16, float> acc[2][4];
#pragma unroll
    for (int i = 0; i < 2; i++)
#pragma unroll
        for (int j = 0; j < 4; j++) wmma::fill_fragment(acc[i][j], 0.f);

#define PREFETCH(K0) do {                                                       \
        _Pragma("unroll")                                                       \
        for (int u = 0; u < 4; u++) {                                           \
            const float4* pa = (const float4*)(s_feat + aoff + (size_t)(32 * u) * D + (K0)); \
            bA[2 * u] = pa[0]; bA[2 * u + 1] = pa[1];                           \
            const float4* pb = (const float4*)(t_feat + boff + (size_t)(32 * u) * D + (K0)); \
            bB[2 * u] = pb[0]; bB[2 * u + 1] = pb[1];                           \
        }                                                                       \
    } while (0)

    PREFETCH((size_t)it0 * KC);

    for (int it = 0; it < niter; ++it) {
        // stage registers -> smem (convert to bf16, accumulate norms)
#pragma unroll
        for (int u = 0; u < 4; u++) {
            const int row = row0 + 32 * u;
            float4 a0 = bA[2 * u], a1 = bA[2 * u + 1];
            nA[u] += a0.x * a0.x + a0.y * a0.y + a0.z * a0.z + a0.w * a0.w
                   + a1.x * a1.x + a1.y * a1.y + a1.z * a1.z + a1.w * a1.w;
            __nv_bfloat162 h0 = __float22bfloat162_rn(make_float2(a0.x, a0.y));
            __nv_bfloat162 h1 = __float22bfloat162_rn(make_float2(a0.z, a0.w));
            __nv_bfloat162 h2 = __float22bfloat162_rn(make_float2(a1.x, a1.y));
            __nv_bfloat162 h3 = __float22bfloat162_rn(make_float2(a1.z, a1.w));
            uint4 wA;
            wA.x = *reinterpret_cast<unsigned*>(&h0);
            wA.y = *reinterpret_cast<unsigned*>(&h1);
            wA.z = *reinterpret_cast<unsigned*>(&h2);
            wA.w = *reinterpret_cast<unsigned*>(&h3);
            *(uint4*)&smA[row * LDT + seg * 8] = wA;

            float4 b0 = bB[2 * u], b1 = bB[2 * u + 1];
            nB[u] += b0.x * b0.x + b0.y * b0.y + b0.z * b0.z + b0.w * b0.w
                   + b1.x * b1.x + b1.y * b1.y + b1.z * b1.z + b1.w * b1.w;
            __nv_bfloat162 g0 = __float22bfloat162_rn(make_float2(b0.x, b0.y));
            __nv_bfloat162 g1 = __float22bfloat162_rn(make_float2(b0.z, b0.w));
            __nv_bfloat162 g2 = __float22bfloat162_rn(make_float2(b1.x, b1.y));
            __nv_bfloat162 g3 = __float22bfloat162_rn(make_float2(b1.z, b1.w));
            uint4 wB;
            wB.x = *reinterpret_cast<unsigned*>(&g0);
            wB.y = *reinterpret_cast<unsigned*>(&g1);
            wB.z = *reinterpret_cast<unsigned*>(&g2);
            wB.w = *reinterpret_cast<unsigned*>(&g3);
            *(uint4*)&smB[row * LDT + seg * 8] = wB;
        }
        __syncthreads();

        // issue next tile's loads BEFORE the MMA section (latency hidden by MMA)
        if (it + 1 < niter) PREFETCH((size_t)(it0 + it + 1) * KC);

#pragma unroll
        for (int kk = 0; kk < KC; kk += 16) {
            wmma::fragment<wmma::matrix_a, 16, 16, 16, __nv_bfloat16, wmma::row_major> af[2];
            wmma::fragment<wmma::matrix_b, 16, 16, 16, __nv_bfloat16, wmma::col_major> bf[4];
#pragma unroll
            for (int i = 0; i < 2; i++)
                wmma::load_matrix_sync(af[i], &smA[(wm * 32 + i * 16) * LDT + kk], LDT);
#pragma unroll
            for (int j = 0; j < 4; j++)
                wmma::load_matrix_sync(bf[j], &smB[(wn * 64 + j * 16) * LDT + kk], LDT);
#pragma unroll
            for (int i = 0; i < 2; i++)
#pragma unroll
                for (int j = 0; j < 4; j++)
                    wmma::mma_sync(acc[i][j], af[i], bf[j], acc[i][j]);
        }
        __syncthreads();
    }
#undef PREFETCH

    // Row-norm partials: 8 consecutive lanes share one row; plain stores (no atomics).
#pragma unroll
    for (int u = 0; u < 4; u++) {
        const int row = row0 + 32 * u;
        float va = nA[u];
        va += __shfl_down_sync(0xffffffffu, va, 4, 8);
        va += __shfl_down_sync(0xffffffffu, va, 2, 8);
        va += __shfl_down_sync(0xffffffffu, va, 1, 8);
        if ((lane & 7) == 0 && blockIdx.y == 0) g_s2p[z * B + m0 + row] = va;
        float vb = nB[u];
        vb += __shfl_down_sync(0xffffffffu, vb, 4, 8);
        vb += __shfl_down_sync(0xffffffffu, vb, 2, 8);
        vb += __shfl_down_sync(0xffffffffu, vb, 1, 8);
        if ((lane & 7) == 0 && blockIdx.x == 0) g_t2p[z * B + n0 + row] = vb;
    }

    // Epilogue: plain stores of this z-slice's partials
    float* base = g_part + (size_t)z * B * B;
#pragma unroll
    for (int i = 0; i < 2; i++)
#pragma unroll
        for (int j = 0; j < 4; j++) {
            const int r0 = m0 + wm * 32 + i * 16;
            const int c0 = n0 + wn * 64 + j * 16;
            wmma::store_matrix_sync(base + (size_t)r0 * B + c0, acc[i][j], B,
                                    wmma::mem_row_major);
        }
}

// One block per row i (grid=256): thread j reduces its own z-column of g_part
// (37 independent L2 loads -> high MLP, full-chip parallelism), builds masked sq
// row in smem; warp 0 runs the shfl top-k; last block fuses the logit losses.
__global__ void __launch_bounds__(256) topk_kernel(const int* __restrict__ labels,
                                                   const int* __restrict__ kptr,
                                                   const float* __restrict__ t_logits,
                                                   const float* __restrict__ s_logits,
                                                   const int* __restrict__ tptr,
                                                   float* __restrict__ out) {
    const int i = blockIdx.x;
    const int j = threadIdx.x;
    const int lane = j & 31, warp = j >> 5;
    const float BIG = 3e38f;

    // per-thread z-reductions (independent loads, unrolled for MLP)
    float dot = 0.f, t2 = 0.f;
#pragma unroll 4
    for (int z = 0; z < KSPLIT; z++) {
        dot += g_part[(size_t)z * B * B + (size_t)i * B + j];
        t2  += g_t2p[z * B + j];
    }
    // s2[i]: 37 partials reduced across the block
    float s2part = (j < KSPLIT) ? g_s2p[j * B + i] : 0.f;
    __shared__ float s2red[64];
    if (j < 64) s2red[j] = 0.f;
    __syncthreads();
    if (j < KSPLIT) s2red[j] = s2part;
    __syncthreads();
    __shared__ float s2sh;
    if (j == 0) {
        float s = 0.f;
#pragma unroll
        for (int z = 0; z < 64; z++) s += s2red[z];
        s2sh = s;
    }
    __shared__ int lish;
    if (j == 0) lish = labels[i];
    __syncthreads();
    const float s2i = s2sh;
    const int li = lish;

    __shared__ float sq[B];
    sq[j] = (labels[j] == li) ? fmaxf(s2i + t2 - 2.f * dot, 0.f) : BIG;
    __syncthreads();

    __shared__ float blocksum;
    if (warp == 0) {
        float v[8];
#pragma unroll
        for (int t = 0; t < 8; t++) v[t] = sq[lane + 32 * t];

        int k = kptr ? kptr[0] : 5;
        if (k > B) k = B;
        if (k < 0) k = 0;

        float ssum = 0.f;
        for (int r = 0; r < k; ++r) {
            float m = v[0];
#pragma unroll
            for (int t = 1; t < 8; t++) m = fminf(m, v[t]);
#pragma unroll
            for (int off = 16; off > 0; off >>= 1)
                m = fminf(m, __shfl_xor_sync(0xffffffffu, m, off));
            if (m >= 1e37f) break;  // fewer than k same-label entries
            bool has = false;
#pragma unroll
            for (int t = 0; t < 8; t++) has |= (v[t] == m);
            unsigned bal = __ballot_sync(0xffffffffu, has);
            int win = __ffs(bal) - 1;
            if (lane == win) {
                bool done = false;
#pragma unroll
                for (int t = 0; t < 8; t++)
                    if (!done && v[t] == m) { v[t] = BIG; done = true; }
            }
            if (lane == 0) ssum += m;
        }
        if (lane == 0) blocksum = ssum;
    }
    __syncthreads();

    // last-block-finishes: accumulate, then fused logit losses
    __shared__ float sh_total;
    __shared__ int   sh_last;
    if (j == 0) {
        atomicAdd(&g_acc, blocksum);
        __threadfence();
        int c = atomicAdd(&g_counter, 1);
        if (c == (int)gridDim.x - 1) {
            sh_total  = atomicAdd(&g_acc, 0.f);  // all adds visible (fenced before counter)
            sh_last   = 1;
            g_counter = 0;   // self-reset for next graph replay
            g_acc     = 0.f;
        } else {
            sh_last = 0;
        }
    }
    __syncthreads();

    if (sh_last) {
        const int b = threadIdx.x;
        const float T = tptr ? (float)tptr[0] : 4.f;

        float s0 = s_logits[2 * b], s1 = s_logits[2 * b + 1];
        float m = fmaxf(s0, s1);
        float lse = m + logf(expf(s0 - m) + expf(s1 - m));
        int lab = labels[b];
        float tr = lse - (lab ? s1 : s0);

        float t0 = t_logits[2 * b] / T, t1 = t_logits[2 * b + 1] / T;
        float mt = fmaxf(t0, t1);
        float e0 = expf(t0 - mt), e1 = expf(t1 - mt);
        float Z = e0 + e1;
        float p0 = e0 / Z, p1 = e1 / Z;
        float q0 = s0 / T, q1 = s1 / T;
        float mq = fmaxf(q0, q1);
        float lseq = mq + logf(expf(q0 - mq) + expf(q1 - mq));
        float soft = p0 * (logf(p0) - (q0 - lseq)) + p1 * (logf(p1) - (q1 - lseq));

        float trs = block_reduce_sum(tr);
        float sfs = block_reduce_sum(soft);
        if (b == 0) {
            out[0] = trs / (float)B;
            out[1] = sfs / (float)B * T * T;
            out[2] = sh_total / (float)D;
        }
    }
}

extern "C" void kernel_launch(void* const* d_in, const int* in_sizes, int n_in,
                              void* d_out, int out_size) {
    const float* t_logits = (const float*)d_in[0];
    const float* s_logits = (const float*)d_in[1];
    const float* t_feat   = (const float*)d_in[2];
    const float* s_feat   = (const float*)d_in[3];
    const int*   labels   = (const int*)d_in[4];            // int32 (JAX x64 disabled)
    const int*   kptr     = (n_in > 5) ? (const int*)d_in[5] : nullptr;
    const int*   tptr     = (n_in > 6) ? (const int*)d_in[6] : nullptr;
    float* out = (float*)d_out;

    gemm_kernel<<<dim3(2, 2, KSPLIT), 256>>>(s_feat, t_feat);
    topk_kernel<<<B, 256>>>(labels, kptr, t_logits, s_logits, tptr, out);
}